// round 1
// baseline (speedup 1.0000x reference)
#include <cuda_runtime.h>
#include <cuda_bf16.h>
#include <cstdint>

// Problem constants (shapes fixed by setup_inputs)
#define HW      (1024 * 1024)     // pixels per channel
#define NBINS   16
#define NTOT    (NBINS * NBINS * NBINS)   // 4096
#define NIMG    9                  // 8 input images + 1 style image
#define BPI     128                // blocks per image
#define TPB     256                // threads per block

// Global scratch: per-image integer histograms (exact counts).
__device__ int g_hist[NIMG][NTOT];

// ---------------------------------------------------------------------------
// Kernel 1: zero the global histograms (graph replays need fresh state)
// ---------------------------------------------------------------------------
__global__ void zero_hist_kernel() {
    int idx = blockIdx.x * blockDim.x + threadIdx.x;
    if (idx < NIMG * NTOT) {
        ((int*)g_hist)[idx] = 0;
    }
}

// searchsorted(boundaries, v, side='left') with boundaries = i/8 - 1, i=1..15.
// = count of boundaries strictly < v = clamp(ceil(8*(v+1)) - 1, 0, 15).
__device__ __forceinline__ int bin_of(float v) {
    float t = (v + 1.0f) * 8.0f;
    int i = (int)ceilf(t) - 1;
    i = i < 0 ? 0 : i;
    i = i > 15 ? 15 : i;
    return i;
}

__device__ __forceinline__ int flat_bin(float r, float g, float b) {
    return bin_of(r) + (bin_of(g) << 4) + (bin_of(b) << 8);
}

// ---------------------------------------------------------------------------
// Kernel 2: per-image histogram. gridDim = (BPI, NIMG), block = TPB threads.
// Shared 4096-bin int histogram per CTA, flushed with global atomics.
// ---------------------------------------------------------------------------
__global__ __launch_bounds__(TPB) void hist_kernel(
    const float* __restrict__ inp,   // [8, 3, H, W]
    const float* __restrict__ sty)   // [1, 3, H, W]
{
    __shared__ int sh[NTOT];
    #pragma unroll
    for (int i = threadIdx.x; i < NTOT; i += TPB) sh[i] = 0;
    __syncthreads();

    const int img = blockIdx.y;
    const float* base = (img < 8) ? (inp + (size_t)img * 3 * HW) : sty;

    const float4* r4 = (const float4*)(base);
    const float4* g4 = (const float4*)(base + HW);
    const float4* b4 = (const float4*)(base + 2 * HW);

    const int nvec      = HW / 4;          // 262144 float4 per channel
    const int per_block = nvec / BPI;      // 2048
    const int start     = blockIdx.x * per_block;
    const int end       = start + per_block;

    for (int i = start + threadIdx.x; i < end; i += TPB) {
        float4 r = r4[i];
        float4 g = g4[i];
        float4 b = b4[i];

        int f0 = flat_bin(r.x, g.x, b.x);
        int f1 = flat_bin(r.y, g.y, b.y);
        int f2 = flat_bin(r.z, g.z, b.z);
        int f3 = flat_bin(r.w, g.w, b.w);

        atomicAdd(&sh[f0], 1);
        atomicAdd(&sh[f1], 1);
        atomicAdd(&sh[f2], 1);
        atomicAdd(&sh[f3], 1);
    }
    __syncthreads();

    #pragma unroll
    for (int i = threadIdx.x; i < NTOT; i += TPB) {
        int v = sh[i];
        if (v) atomicAdd(&g_hist[img][i], v);
    }
}

// ---------------------------------------------------------------------------
// Kernel 3: loss = mean_b,j | h[b][j]/HW - h[style][j]/HW |
//         = (1/(8*4096*HW)) * sum_b,j |h[b][j] - h[style][j]|  (exact ints)
// ---------------------------------------------------------------------------
__global__ __launch_bounds__(512) void loss_kernel(float* __restrict__ out) {
    __shared__ long long red[512];

    long long acc = 0;
    for (int idx = threadIdx.x; idx < 8 * NTOT; idx += 512) {
        int b = idx >> 12;
        int j = idx & (NTOT - 1);
        int d = g_hist[b][j] - g_hist[8][j];
        acc += (long long)(d < 0 ? -d : d);
    }
    red[threadIdx.x] = acc;
    __syncthreads();

    for (int s = 256; s > 0; s >>= 1) {
        if (threadIdx.x < s) red[threadIdx.x] += red[threadIdx.x + s];
        __syncthreads();
    }

    if (threadIdx.x == 0) {
        double total = (double)red[0];
        out[0] = (float)(total / ((double)HW * 8.0 * (double)NTOT));
    }
}

// ---------------------------------------------------------------------------
// Launch contract
// ---------------------------------------------------------------------------
extern "C" void kernel_launch(void* const* d_in, const int* in_sizes, int n_in,
                              void* d_out, int out_size)
{
    const float* inp = (const float*)d_in[0];   // [8,3,1024,1024] fp32
    const float* sty = (const float*)d_in[1];   // [1,3,1024,1024] fp32
    float* out = (float*)d_out;

    zero_hist_kernel<<<(NIMG * NTOT + 255) / 256, 256>>>();
    dim3 grid(BPI, NIMG);
    hist_kernel<<<grid, TPB>>>(inp, sty);
    loss_kernel<<<1, 512>>>(out);
}